// round 1
// baseline (speedup 1.0000x reference)
#include <cuda_runtime.h>
#include <math.h>

#define NAq 1152
#define NDq 736
#define NPq 512
#define PADq 2048

// ---- geometry in double (compile-time folded) ----
#define VOXd (1.0 / 0.7)
#define Dd   (VOXd * 595.0)
#define DDd  (VOXd * 490.6)
#define DUd  (VOXd * 1.2858)
#define DSDd (Dd + DDd)

// ---- device scratch (static allocation: allowed) ----
__device__ float g_filt[1025];
__device__ float g_hext[1472];          // h[|i-735|] * pi/(2*NA), i in [0,1470]
__device__ float g_cos[NAq];
__device__ float g_sin[NAq];
__device__ float g_flt[NAq * NDq];      // filtered sinogram

__device__ __forceinline__ float frcp(float x) {
    float r;
    asm("rcp.approx.f32 %0, %1;" : "=f"(r) : "f"(x));
    return r;
}

// ---------------------------------------------------------------------------
// Stage 0a: FILT[k] = 2*Re(FFT(f))[k] * ShepLoganWindow, k = 0..1024
// f[0]=0.25; f[j] = -1/(pi*min(j,2048-j))^2 for odd j (even-symmetric).
// four[k] = 0.5 - (4/pi^2) * sum_{m=0}^{511} cos(2*pi*k*(2m+1)/2048)/(2m+1)^2
// ---------------------------------------------------------------------------
__global__ void filt_kernel() {
    int k = blockIdx.x * blockDim.x + threadIdx.x;
    if (k > 1024) return;
    double s = 0.0;
    for (int m = 0; m < 512; m++) {
        int j = 2 * m + 1;
        int p = (k * j) & 2047;                       // exact phase mod 2048
        float c = cospif((float)p * (1.0f / 1024.0f)); // cos(2*pi*p/2048)
        s += (double)(c / ((float)j * (float)j));
    }
    double four = 0.5 - (4.0 / (M_PI * M_PI)) * s;
    if (k > 0) {
        double om = M_PI * (double)k / 2048.0;
        four *= sin(om) / om;                          // Shepp-Logan window
    }
    g_filt[k] = (float)four;
}

// ---------------------------------------------------------------------------
// Stage 0b: spatial kernel h[d] = irfft(FILT)[d], d = 0..735 (h is even).
// h[d] = (FILT[0] + (-1)^d * FILT[1024] + 2*sum_{k=1}^{1023} FILT[k]*cos(2*pi*k*d/2048)) / 2048
// Scaled by pi/(2*NA). Stored as extended kernel hext[735 +- d].
// ---------------------------------------------------------------------------
__global__ void hker_kernel() {
    int d = blockIdx.x * blockDim.x + threadIdx.x;
    if (d >= NDq) return;
    double s = (double)g_filt[0] + (double)g_filt[1024] * ((d & 1) ? -1.0 : 1.0);
    for (int k = 1; k <= 1023; k++) {
        int p = (k * d) & 2047;
        s += 2.0 * (double)g_filt[k] * (double)cospif((float)p * (1.0f / 1024.0f));
    }
    float h = (float)(s * (1.0 / 2048.0) * (M_PI / (2.0 * (double)NAq)));
    g_hext[735 - d] = h;
    g_hext[735 + d] = h;
}

// ---------------------------------------------------------------------------
// Stage 0c: angle tables (double trig, cast to float, matches reference)
// ---------------------------------------------------------------------------
__global__ void angle_kernel() {
    int a = blockIdx.x * blockDim.x + threadIdx.x;
    if (a >= NAq) return;
    double beta = 2.0 * M_PI * (double)a / (double)NAq + M_PI / 2.0;
    g_cos[a] = (float)cos(beta);
    g_sin[a] = (float)sin(beta);
}

// ---------------------------------------------------------------------------
// Stage 1: filtering as linear convolution. One block per projection row.
// out[j] = sum_{k=0}^{735} s[k] * hext[j - k + 735]
// ---------------------------------------------------------------------------
__global__ void __launch_bounds__(256) conv_kernel(const float* __restrict__ sino) {
    __shared__ float s_row[NDq];
    __shared__ float s_h[1536];
    int row = blockIdx.x;
    int tid = threadIdx.x;
    const float* src = sino + row * NDq;
    for (int i = tid; i < NDq; i += 256) s_row[i] = src[i];
    for (int i = tid; i < 1536; i += 256) s_h[i] = (i < 1471) ? g_hext[i] : 0.0f;
    __syncthreads();

    float a0 = 0.f, a1 = 0.f, a2 = 0.f;
    const float* h0 = s_h + tid + 735;
    const float* h1 = h0 + 256;
    const float* h2 = h1 + 256;
#pragma unroll 4
    for (int k = 0; k < NDq; k++) {
        float sv = s_row[k];
        a0 = fmaf(sv, h0[-k], a0);
        a1 = fmaf(sv, h1[-k], a1);
        a2 = fmaf(sv, h2[-k], a2);
    }
    float* dst = g_flt + row * NDq;
    dst[tid] = a0;
    dst[tid + 256] = a1;
    if (tid < NDq - 512) dst[tid + 512] = a2;
}

// ---------------------------------------------------------------------------
// Stage 2: fan-beam backprojection + fused HU normalization.
// 32x32 pixel tile per block (grid 16x16), 256 threads x 4 consecutive x.
// Filtered row double-buffered in smem, prefetched with LDG.128.
// ---------------------------------------------------------------------------
__global__ void __launch_bounds__(256) bp_kernel(float* __restrict__ out) {
    __shared__ float s_row[2][NDq];
    int tid = threadIdx.x;
    int qx = tid & 7;          // 8 x-groups of 4
    int ty = tid >> 3;         // 32 rows
    int x0 = blockIdx.x * 32 + qx * 4;
    int y  = blockIdx.y * 32 + ty;

    float xs = (float)x0 - 255.5f;
    float ys = (float)y  - 255.5f;

    const float Df = (float)Dd;
    const float K  = (float)(DSDd / DUd);
    const float C  = ((float)NDq - 1.0f) * 0.5f;   // 367.5

    // preload row 0
    if (tid < NDq / 4)
        ((float4*)s_row[0])[tid] = ((const float4*)g_flt)[tid];
    __syncthreads();

    float acc[4] = {0.f, 0.f, 0.f, 0.f};

    for (int a = 0; a < NAq; a++) {
        float4 pf;
        bool doPf = (a + 1 < NAq) && (tid < NDq / 4);
        if (doPf) pf = ((const float4*)(g_flt + (a + 1) * NDq))[tid];

        float cb = g_cos[a];
        float sb = g_sin[a];
        const float* row = s_row[a & 1];

        float den = Df - fmaf(xs, cb, ys * sb);   // D - (x*cb + y*sb)
        float pe  = fmaf(ys, cb, -xs * sb);       // -x*sb + y*cb

#pragma unroll
        for (int i = 0; i < 4; i++) {
            float r  = frcp(den);                  // 1/den  (den > 488 always)
            float iu = fmaf(K * pe, r, C);         // fractional detector index
            int   i0 = __float2int_rd(iu);
            float fr = iu - __int2float_rn(i0);
            int   ic = min(max(i0, 0), NDq - 2);
            float v0 = row[ic];
            float v1 = row[ic + 1];
            float v  = fmaf(fr, v1 - v0, v0);
            float w  = r * r;                      // (1/den)^2; D^2 folded in A
            w = ((unsigned)i0 < (unsigned)(NDq - 1)) ? w : 0.0f;
            acc[i] = fmaf(w, v, acc[i]);
            den -= cb;
            pe  -= sb;
        }

        if (doPf) ((float4*)s_row[(a + 1) & 1])[tid] = pf;
        __syncthreads();
    }

    // fbp = D^2 * acc;  out = fbp * 1000/(0.0192*4096) + 24/4096
    const float A = (float)((Dd * Dd) * (1000.0 / 0.0192) / 4096.0);
    const float B = (float)(24.0 / 4096.0);

    float4 o;
    o.x = fmaf(A, acc[0], B);
    o.y = fmaf(A, acc[1], B);
    o.z = fmaf(A, acc[2], B);
    o.w = fmaf(A, acc[3], B);
    ((float4*)(out + y * NPq + x0))[0] = o;
}

// ---------------------------------------------------------------------------
extern "C" void kernel_launch(void* const* d_in, const int* in_sizes, int n_in,
                              void* d_out, int out_size) {
    const float* sino = (const float*)d_in[0];
    float* out = (float*)d_out;

    filt_kernel<<<9, 128>>>();        // 1025 values
    hker_kernel<<<6, 128>>>();        // 736 values
    angle_kernel<<<9, 128>>>();       // 1152 angles
    conv_kernel<<<NAq, 256>>>(sino);  // filtered sinogram
    dim3 grid(NPq / 32, NPq / 32);    // 16 x 16 tiles
    bp_kernel<<<grid, 256>>>(out);
}

// round 2
// speedup vs baseline: 2.0999x; 2.0999x over previous
#include <cuda_runtime.h>
#include <math.h>

#define NAq 1152
#define NDq 736
#define NPq 512

// ---- geometry in double (compile-time folded) ----
#define VOXd (1.0 / 0.7)
#define Dd   (VOXd * 595.0)
#define DDd  (VOXd * 490.6)
#define DUd  (VOXd * 1.2858)
#define DSDd (Dd + DDd)

// ---- device scratch (static allocation: allowed) ----
__device__ float g_filt[1025];
__device__ float g_hext[1472];          // h[|i-735|] * pi/(2*NA), i in [0,1470]
__device__ float g_cos[NAq];
__device__ float g_sin[NAq];
__device__ float g_flt[NAq * NDq];      // filtered sinogram

__device__ __forceinline__ float frcp(float x) {
    float r;
    asm("rcp.approx.f32 %0, %1;" : "=f"(r) : "f"(x));
    return r;
}

// ---------------------------------------------------------------------------
// Stage 0a: FILT[k] = 2*Re(FFT(f))[k] * ShepLoganWindow, k = 0..1024
// four[k] = 0.5 - (4/pi^2) * sum_{m} cos(2*pi*k*(2m+1)/2048)/(2m+1)^2
// 4-way partial sums break the serial double-add latency chain.
// ---------------------------------------------------------------------------
__global__ void filt_kernel() {
    int k = blockIdx.x * blockDim.x + threadIdx.x;
    if (k > 1024) return;
    double s0 = 0.0, s1 = 0.0, s2 = 0.0, s3 = 0.0;
    for (int m = 0; m < 512; m += 4) {
        int j0 = 2 * m + 1, j1 = j0 + 2, j2 = j0 + 4, j3 = j0 + 6;
        float c0 = cospif((float)((k * j0) & 2047) * (1.0f / 1024.0f));
        float c1 = cospif((float)((k * j1) & 2047) * (1.0f / 1024.0f));
        float c2 = cospif((float)((k * j2) & 2047) * (1.0f / 1024.0f));
        float c3 = cospif((float)((k * j3) & 2047) * (1.0f / 1024.0f));
        s0 += (double)(c0 / ((float)j0 * (float)j0));
        s1 += (double)(c1 / ((float)j1 * (float)j1));
        s2 += (double)(c2 / ((float)j2 * (float)j2));
        s3 += (double)(c3 / ((float)j3 * (float)j3));
    }
    double four = 0.5 - (4.0 / (M_PI * M_PI)) * ((s0 + s1) + (s2 + s3));
    if (k > 0) {
        double om = M_PI * (double)k / 2048.0;
        four *= sin(om) / om;                          // Shepp-Logan window
    }
    g_filt[k] = (float)four;
}

// ---------------------------------------------------------------------------
// Stage 0b: spatial kernel h[d] = irfft(FILT)[d], d = 0..735 (h is even).
// ---------------------------------------------------------------------------
__global__ void hker_kernel() {
    int d = blockIdx.x * blockDim.x + threadIdx.x;
    if (d >= NDq) return;
    double s0 = 0.0, s1 = 0.0, s2 = 0.0, s3 = 0.0;
    for (int k = 1; k <= 1020; k += 4) {
        s0 += (double)g_filt[k]     * (double)cospif((float)((k * d) & 2047) * (1.0f / 1024.0f));
        s1 += (double)g_filt[k + 1] * (double)cospif((float)(((k + 1) * d) & 2047) * (1.0f / 1024.0f));
        s2 += (double)g_filt[k + 2] * (double)cospif((float)(((k + 2) * d) & 2047) * (1.0f / 1024.0f));
        s3 += (double)g_filt[k + 3] * (double)cospif((float)(((k + 3) * d) & 2047) * (1.0f / 1024.0f));
    }
    // tail k = 1021..1023
    for (int k = 1021; k <= 1023; k++) {
        s0 += (double)g_filt[k] * (double)cospif((float)((k * d) & 2047) * (1.0f / 1024.0f));
    }
    double s = (double)g_filt[0] + (double)g_filt[1024] * ((d & 1) ? -1.0 : 1.0)
             + 2.0 * ((s0 + s1) + (s2 + s3));
    float h = (float)(s * (1.0 / 2048.0) * (M_PI / (2.0 * (double)NAq)));
    g_hext[735 - d] = h;
    g_hext[735 + d] = h;
}

// ---------------------------------------------------------------------------
// Stage 0c: angle tables
// ---------------------------------------------------------------------------
__global__ void angle_kernel() {
    int a = blockIdx.x * blockDim.x + threadIdx.x;
    if (a >= NAq) return;
    double beta = 2.0 * M_PI * (double)a / (double)NAq + M_PI / 2.0;
    g_cos[a] = (float)cos(beta);
    g_sin[a] = (float)sin(beta);
}

// ---------------------------------------------------------------------------
// Stage 1: filtering as linear convolution. 4 rows per block: the s_row[k]
// broadcast LDS is shared across rows, h loads are row-independent.
// Per k: 4 bcast LDS + 3 h LDS + 12 FMA (was 4 LDS per 3 FMA).
// ---------------------------------------------------------------------------
#define RB 4
__global__ void __launch_bounds__(256) conv_kernel(const float* __restrict__ sino) {
    __shared__ float s_s[RB][NDq];
    __shared__ float s_h[1536];
    int tid = threadIdx.x;
    int row0 = blockIdx.x * RB;
#pragma unroll
    for (int r = 0; r < RB; r++)
        for (int i = tid; i < NDq; i += 256)
            s_s[r][i] = sino[(row0 + r) * NDq + i];
    for (int i = tid; i < 1536; i += 256) s_h[i] = (i < 1471) ? g_hext[i] : 0.0f;
    __syncthreads();

    float acc[RB][3] = {};
    const float* h0 = s_h + tid + 735;
#pragma unroll 4
    for (int k = 0; k < NDq; k++) {
        float hv0 = h0[-k];
        float hv1 = h0[256 - k];
        float hv2 = h0[512 - k];
#pragma unroll
        for (int r = 0; r < RB; r++) {
            float sv = s_s[r][k];
            acc[r][0] = fmaf(sv, hv0, acc[r][0]);
            acc[r][1] = fmaf(sv, hv1, acc[r][1]);
            acc[r][2] = fmaf(sv, hv2, acc[r][2]);
        }
    }
#pragma unroll
    for (int r = 0; r < RB; r++) {
        float* dst = g_flt + (row0 + r) * NDq;
        dst[tid] = acc[r][0];
        dst[tid + 256] = acc[r][1];
        if (tid < NDq - 512) dst[tid + 512] = acc[r][2];
    }
}

// ---------------------------------------------------------------------------
// Stage 2: fan-beam backprojection + fused HU normalization.
// 32x32 pixel tile per block (grid 16x16), 256 threads x 4 consecutive x.
// 8 angles per smem chunk, double-buffered: ONE barrier per 8 angles, and the
// next chunk's LDG (6 float4/thread) is in flight across 8 angles of compute.
// 1/den via one rcp + 2nd-order series along x (err ~2e-7 rel).
// ---------------------------------------------------------------------------
#define CH 8
#define NCH (NAq / CH)          // 144
#define CHF (CH * NDq)          // 5888 floats per chunk
#define CHF4 (CHF / 4)          // 1472 float4

__global__ void __launch_bounds__(256) bp_kernel(float* __restrict__ out) {
    __shared__ float sbuf[2][CHF];     // 2 * 23552 B = 47104 B
    int tid = threadIdx.x;
    int qx = tid & 7;          // 8 x-groups of 4
    int ty = tid >> 3;         // 32 rows
    int x0 = blockIdx.x * 32 + qx * 4;
    int y  = blockIdx.y * 32 + ty;

    float xs = (float)x0 - 255.5f;
    float ys = (float)y  - 255.5f;

    const float Df = (float)Dd;
    const float K  = (float)(DSDd / DUd);
    const float C  = ((float)NDq - 1.0f) * 0.5f;   // 367.5

    // preload chunk 0
    {
        const float4* src = (const float4*)g_flt;
        float4* dst = (float4*)sbuf[0];
#pragma unroll
        for (int j = 0; j < 6; j++) {
            int idx = tid + j * 256;
            if (idx < CHF4) dst[idx] = src[idx];
        }
    }
    __syncthreads();

    float acc[4] = {0.f, 0.f, 0.f, 0.f};

    for (int c = 0; c < NCH; c++) {
        float4 pf[6];
        bool more = (c + 1 < NCH);
        if (more) {
            const float4* src = (const float4*)(g_flt + (c + 1) * CHF);
#pragma unroll
            for (int j = 0; j < 6; j++) {
                int idx = tid + j * 256;
                if (idx < CHF4) pf[j] = src[idx];
            }
        }

        const float* buf = sbuf[c & 1];
#pragma unroll
        for (int aa = 0; aa < CH; aa++) {
            int a = c * CH + aa;
            float cb = __ldg(&g_cos[a]);
            float sb = __ldg(&g_sin[a]);
            const float* row = buf + aa * NDq;

            float den = Df - fmaf(xs, cb, ys * sb);    // D - (x*cb + y*sb)
            float peK = fmaf(ys, cb, -xs * sb) * K;    // K * (-x*sb + y*cb)
            float sbK = sb * K;
            float r0  = frcp(den);                     // den in [488, 1212]
            float e   = cb * r0;
            float t   = 0.0f;
            float r   = r0;

#pragma unroll
            for (int i = 0; i < 4; i++) {
                float iu = fmaf(peK, r, C);            // fractional det index
                int   i0 = __float2int_rd(iu);
                float fr = iu - __int2float_rn(i0);
                int   ic = min(max(i0, 0), NDq - 2);
                float v0 = row[ic];
                float v1 = row[ic + 1];
                float v  = fmaf(fr, v1 - v0, v0);
                float w  = r * r;
                w = ((unsigned)i0 < (unsigned)(NDq - 1)) ? w : 0.0f;
                acc[i] = fmaf(w, v, acc[i]);
                // advance one pixel in x: r = 1/(den - (i+1)*cb) via series
                t += e;
                peK -= sbK;
                float f = fmaf(t, t, t);               // t + t^2
                r = fmaf(r0, f, r0);                   // r0 * (1 + t + t^2)
            }
        }

        if (more) {
            float4* dst = (float4*)sbuf[(c + 1) & 1];
#pragma unroll
            for (int j = 0; j < 6; j++) {
                int idx = tid + j * 256;
                if (idx < CHF4) dst[idx] = pf[j];
            }
        }
        __syncthreads();
    }

    // fbp = D^2 * acc;  out = fbp * 1000/(0.0192*4096) + 24/4096
    const float A = (float)((Dd * Dd) * (1000.0 / 0.0192) / 4096.0);
    const float B = (float)(24.0 / 4096.0);

    float4 o;
    o.x = fmaf(A, acc[0], B);
    o.y = fmaf(A, acc[1], B);
    o.z = fmaf(A, acc[2], B);
    o.w = fmaf(A, acc[3], B);
    ((float4*)(out + y * NPq + x0))[0] = o;
}

// ---------------------------------------------------------------------------
extern "C" void kernel_launch(void* const* d_in, const int* in_sizes, int n_in,
                              void* d_out, int out_size) {
    const float* sino = (const float*)d_in[0];
    float* out = (float*)d_out;

    filt_kernel<<<9, 128>>>();              // 1025 values
    hker_kernel<<<6, 128>>>();              // 736 values
    angle_kernel<<<9, 128>>>();             // 1152 angles
    conv_kernel<<<NAq / RB, 256>>>(sino);   // filtered sinogram, 4 rows/block
    dim3 grid(NPq / 32, NPq / 32);          // 16 x 16 tiles
    bp_kernel<<<grid, 256>>>(out);
}

// round 4
// speedup vs baseline: 3.0684x; 1.4612x over previous
#include <cuda_runtime.h>
#include <cstdint>
#include <math.h>

#define NAq 1152
#define NDq 736
#define NPq 512

#define SPLIT 4
#define APB (NAq / SPLIT)      // 288 angles per bp block
#define CH 4
#define NCHb (APB / CH)        // 72 chunks
#define CHP (CH * NDq)         // float2 entries per chunk (2944)
#define CHP4 (CHP / 2)         // float4 loads per chunk (1472)

// ---- geometry in double (compile-time folded) ----
#define VOXd (1.0 / 0.7)
#define Dd   (VOXd * 595.0)
#define DDd  (VOXd * 490.6)
#define DUd  (VOXd * 1.2858)
#define DSDd (Dd + DDd)

// ---- device scratch (static allocation: allowed) ----
__device__ float  g_filt[1025];
__device__ float  g_hext[1472];          // h[|i-735|] * pi/(2*NA)
__device__ float  g_cos[NAq];
__device__ float  g_sin[NAq];
__device__ float2 g_fp2[NAq * NDq];      // filtered rows as (v, v_next - v)
__device__ float  g_part[SPLIT][NPq * NPq];

__device__ __forceinline__ float frcp(float x) {
    float r;
    asm("rcp.approx.f32 %0, %1;" : "=f"(r) : "f"(x));
    return r;
}

__device__ __forceinline__ void cpasync16(unsigned int s, const void* g) {
    asm volatile("cp.async.cg.shared.global [%0], [%1], 16;" :: "r"(s), "l"(g));
}
__device__ __forceinline__ void cpasync_commit() {
    asm volatile("cp.async.commit_group;");
}
__device__ __forceinline__ void cpasync_wait0() {
    asm volatile("cp.async.wait_group 0;");
}

// ---------------------------------------------------------------------------
// Stage 0a: FILT[k] = 2*Re(FFT(f))[k] * Shepp-Logan window, k = 0..1024
// four[k] = 0.5 - (4/pi^2) * sum_m cos(2*pi*k*(2m+1)/2048)/(2m+1)^2
// ---------------------------------------------------------------------------
__global__ void filt_kernel() {
    int k = blockIdx.x * blockDim.x + threadIdx.x;
    if (k > 1024) return;
    double s0 = 0.0, s1 = 0.0, s2 = 0.0, s3 = 0.0;
    for (int m = 0; m < 512; m += 4) {
        int j0 = 2 * m + 1, j1 = j0 + 2, j2 = j0 + 4, j3 = j0 + 6;
        float c0 = cospif((float)((k * j0) & 2047) * (1.0f / 1024.0f));
        float c1 = cospif((float)((k * j1) & 2047) * (1.0f / 1024.0f));
        float c2 = cospif((float)((k * j2) & 2047) * (1.0f / 1024.0f));
        float c3 = cospif((float)((k * j3) & 2047) * (1.0f / 1024.0f));
        s0 += (double)(c0 / ((float)j0 * (float)j0));
        s1 += (double)(c1 / ((float)j1 * (float)j1));
        s2 += (double)(c2 / ((float)j2 * (float)j2));
        s3 += (double)(c3 / ((float)j3 * (float)j3));
    }
    double four = 0.5 - (4.0 / (M_PI * M_PI)) * ((s0 + s1) + (s2 + s3));
    if (k > 0) {
        double om = M_PI * (double)k / 2048.0;
        four *= sin(om) / om;
    }
    g_filt[k] = (float)four;
}

// ---------------------------------------------------------------------------
// Stage 0b: h[d] = irfft(FILT)[d]. One block per d, 128 threads + reduction.
// ---------------------------------------------------------------------------
__global__ void __launch_bounds__(128) hker_kernel() {
    __shared__ double red[128];
    int d = blockIdx.x;
    int tid = threadIdx.x;
    double s = 0.0;
    for (int k = 1 + tid; k <= 1023; k += 128) {
        s += (double)g_filt[k] * (double)cospif((float)((k * d) & 2047) * (1.0f / 1024.0f));
    }
    red[tid] = s;
    __syncthreads();
    for (int w = 64; w > 0; w >>= 1) {
        if (tid < w) red[tid] += red[tid + w];
        __syncthreads();
    }
    if (tid == 0) {
        double t = (double)g_filt[0] + (double)g_filt[1024] * ((d & 1) ? -1.0 : 1.0)
                 + 2.0 * red[0];
        float h = (float)(t * (1.0 / 2048.0) * (M_PI / (2.0 * (double)NAq)));
        g_hext[735 - d] = h;
        g_hext[735 + d] = h;
    }
}

// ---------------------------------------------------------------------------
// Stage 0c: angle tables
// ---------------------------------------------------------------------------
__global__ void angle_kernel() {
    int a = blockIdx.x * blockDim.x + threadIdx.x;
    if (a >= NAq) return;
    double beta = 2.0 * M_PI * (double)a / (double)NAq + M_PI / 2.0;
    g_cos[a] = (float)cos(beta);
    g_sin[a] = (float)sin(beta);
}

// ---------------------------------------------------------------------------
// Stage 1: filtering as linear convolution, 4 rows/block; emits (v, dv) pairs.
// ---------------------------------------------------------------------------
#define RB 4
__global__ void __launch_bounds__(256) conv_kernel(const float* __restrict__ sino) {
    __shared__ float s_s[RB][NDq];
    __shared__ float s_h[1536];
    int tid = threadIdx.x;
    int row0 = blockIdx.x * RB;
#pragma unroll
    for (int r = 0; r < RB; r++)
        for (int i = tid; i < NDq; i += 256)
            s_s[r][i] = sino[(row0 + r) * NDq + i];
    for (int i = tid; i < 1536; i += 256) s_h[i] = (i < 1471) ? g_hext[i] : 0.0f;
    __syncthreads();

    float acc[RB][3] = {};
    const float* h0 = s_h + tid + 735;
#pragma unroll 4
    for (int k = 0; k < NDq; k++) {
        float hv0 = h0[-k];
        float hv1 = h0[256 - k];
        float hv2 = h0[512 - k];
#pragma unroll
        for (int r = 0; r < RB; r++) {
            float sv = s_s[r][k];
            acc[r][0] = fmaf(sv, hv0, acc[r][0]);
            acc[r][1] = fmaf(sv, hv1, acc[r][1]);
            acc[r][2] = fmaf(sv, hv2, acc[r][2]);
        }
    }
    __syncthreads();
    // stash results back into s_s, then emit (v, v_next - v) pairs
#pragma unroll
    for (int r = 0; r < RB; r++) {
        s_s[r][tid] = acc[r][0];
        s_s[r][tid + 256] = acc[r][1];
        if (tid < NDq - 512) s_s[r][tid + 512] = acc[r][2];
    }
    __syncthreads();
#pragma unroll
    for (int r = 0; r < RB; r++) {
        float2* dst = g_fp2 + (row0 + r) * NDq;
        for (int i = tid; i < NDq; i += 256) {
            float v = s_s[r][i];
            float vn = (i < NDq - 1) ? s_s[r][i + 1] : v;
            dst[i] = make_float2(v, vn - v);
        }
    }
}

// ---------------------------------------------------------------------------
// Stage 2: fan-beam backprojection, 4-way angle split (blockIdx.z).
// 32x32 pixel tile, 256 threads x 4 consecutive x pixels.
// cp.async double-buffered chunks of 4 angles; one LDS.64 gather per sample.
// ---------------------------------------------------------------------------
__global__ void __launch_bounds__(256, 4) bp_kernel() {
    __shared__ float2 sbuf[2][CHP];      // 2 * 23552 B
    int tid = threadIdx.x;
    int z   = blockIdx.z;
    int qx = tid & 7;
    int ty = tid >> 3;
    int x0 = blockIdx.x * 32 + qx * 4;
    int y  = blockIdx.y * 32 + ty;

    float xs = (float)x0 - 255.5f;
    float ys = (float)y  - 255.5f;

    const float Df = (float)Dd;
    const float K  = (float)(DSDd / DUd);
    const float C  = ((float)NDq - 1.0f) * 0.5f;

    unsigned int sb0 = (unsigned int)__cvta_generic_to_shared(&sbuf[0][0]);
    unsigned int sb1 = (unsigned int)__cvta_generic_to_shared(&sbuf[1][0]);
    const float4* gsrc = (const float4*)(g_fp2 + z * APB * NDq);

    // preload chunk 0
#pragma unroll
    for (int j = 0; j < 6; j++) {
        int idx = tid + j * 256;
        if (idx < CHP4) cpasync16(sb0 + idx * 16, gsrc + idx);
    }
    cpasync_commit();
    cpasync_wait0();
    __syncthreads();

    float acc[4] = {0.f, 0.f, 0.f, 0.f};
    int abase = z * APB;

    for (int c = 0; c < NCHb; c++) {
        if (c + 1 < NCHb) {
            const float4* src = gsrc + (c + 1) * CHP4;
            unsigned int dst = (c & 1) ? sb0 : sb1;
#pragma unroll
            for (int j = 0; j < 6; j++) {
                int idx = tid + j * 256;
                if (idx < CHP4) cpasync16(dst + idx * 16, src + idx);
            }
        }
        cpasync_commit();

        const float2* buf = sbuf[c & 1];
#pragma unroll
        for (int aa = 0; aa < CH; aa++) {
            int a = abase + c * CH + aa;
            float cb = __ldg(&g_cos[a]);
            float sb = __ldg(&g_sin[a]);
            const float2* row = buf + aa * NDq;

            float den = Df - fmaf(xs, cb, ys * sb);
            float peK = fmaf(ys, cb, -xs * sb) * K;
            float sbK = sb * K;
            float r0  = frcp(den);                 // den in [488, 1212]
            float e   = cb * r0;
            float t   = 0.0f;
            float r   = r0;

#pragma unroll
            for (int i = 0; i < 4; i++) {
                float iu = fmaf(peK, r, C);
                int   i0 = __float2int_rd(iu);
                float fr = iu - __int2float_rn(i0);
                int   ic = min(max(i0, 0), NDq - 2);
                float2 v = row[ic];
                float val = fmaf(fr, v.y, v.x);
                float w  = r * r;
                w = ((unsigned)i0 < (unsigned)(NDq - 1)) ? w : 0.0f;
                acc[i] = fmaf(w, val, acc[i]);
                // advance one pixel in x: 1/(den-(i+1)*cb) = r0*(1+t+t^2)
                t += e;
                peK -= sbK;
                float f = fmaf(t, t, t);
                r = fmaf(r0, f, r0);
            }
        }

        cpasync_wait0();
        __syncthreads();
    }

    ((float4*)(g_part[z] + y * NPq + x0))[0] = make_float4(acc[0], acc[1], acc[2], acc[3]);
}

// ---------------------------------------------------------------------------
// Stage 3: sum the 4 partial planes + HU normalization.
// ---------------------------------------------------------------------------
__global__ void __launch_bounds__(128) reduce_kernel(float* __restrict__ out) {
    const float A = (float)((Dd * Dd) * (1000.0 / 0.0192) / 4096.0);
    const float B = (float)(24.0 / 4096.0);
    int idx = blockIdx.x * 128 + threadIdx.x;      // float4 index
    float4 p0 = ((const float4*)g_part[0])[idx];
    float4 p1 = ((const float4*)g_part[1])[idx];
    float4 p2 = ((const float4*)g_part[2])[idx];
    float4 p3 = ((const float4*)g_part[3])[idx];
    float4 o;
    o.x = fmaf(A, (p0.x + p1.x) + (p2.x + p3.x), B);
    o.y = fmaf(A, (p0.y + p1.y) + (p2.y + p3.y), B);
    o.z = fmaf(A, (p0.z + p1.z) + (p2.z + p3.z), B);
    o.w = fmaf(A, (p0.w + p1.w) + (p2.w + p3.w), B);
    ((float4*)out)[idx] = o;
}

// ---------------------------------------------------------------------------
extern "C" void kernel_launch(void* const* d_in, const int* in_sizes, int n_in,
                              void* d_out, int out_size) {
    const float* sino = (const float*)d_in[0];
    float* out = (float*)d_out;

    filt_kernel<<<9, 128>>>();              // 1025 values
    hker_kernel<<<NDq, 128>>>();            // 736 values, block-parallel
    angle_kernel<<<9, 128>>>();             // 1152 angles
    conv_kernel<<<NAq / RB, 256>>>(sino);   // filtered sinogram -> (v, dv) pairs
    dim3 grid(NPq / 32, NPq / 32, SPLIT);   // 16 x 16 x 4
    bp_kernel<<<grid, 256>>>();
    reduce_kernel<<<NPq * NPq / 4 / 128, 128>>>(out);
}

// round 5
// speedup vs baseline: 3.2043x; 1.0443x over previous
#include <cuda_runtime.h>
#include <cstdint>
#include <math.h>

#define NAq 1152
#define NDq 736
#define NPq 512

#define SPLIT 4
#define APB (NAq / SPLIT)      // 288 angles per bp block
#define CH 4
#define NCHb (APB / CH)        // 72 chunks
#define CHP (CH * NDq)         // float2 entries per chunk (2944)
#define CHP4 (CHP / 2)         // float4 loads per chunk (1472)

// ---- geometry in double (compile-time folded) ----
#define VOXd (1.0 / 0.7)
#define Dd   (VOXd * 595.0)
#define DDd  (VOXd * 490.6)
#define DUd  (VOXd * 1.2858)
#define DSDd (Dd + DDd)

// ---- device scratch (static allocation: allowed) ----
__device__ float  g_filt[1025];
__device__ float  g_hext[1472];          // h[|i-735|] * pi/(2*NA)
__device__ float  g_cos[NAq];
__device__ float  g_sin[NAq];
__device__ float2 g_fp2[NAq * NDq];      // filtered rows as (v, v_next - v)
__device__ float  g_part[SPLIT][NPq * NPq];

__device__ __forceinline__ float frcp(float x) {
    float r;
    asm("rcp.approx.f32 %0, %1;" : "=f"(r) : "f"(x));
    return r;
}

__device__ __forceinline__ void cpasync16(unsigned int s, const void* g) {
    asm volatile("cp.async.cg.shared.global [%0], [%1], 16;" :: "r"(s), "l"(g));
}
__device__ __forceinline__ void cpasync_commit() {
    asm volatile("cp.async.commit_group;");
}
__device__ __forceinline__ void cpasync_wait0() {
    asm volatile("cp.async.wait_group 0;");
}

// ---------------------------------------------------------------------------
// Stage 0a: FILT[k] = 2*Re(FFT(f))[k] * Shepp-Logan window, k = 0..1024
// ---------------------------------------------------------------------------
__global__ void filt_kernel() {
    int k = blockIdx.x * blockDim.x + threadIdx.x;
    if (k > 1024) return;
    double s0 = 0.0, s1 = 0.0, s2 = 0.0, s3 = 0.0;
    for (int m = 0; m < 512; m += 4) {
        int j0 = 2 * m + 1, j1 = j0 + 2, j2 = j0 + 4, j3 = j0 + 6;
        float c0 = cospif((float)((k * j0) & 2047) * (1.0f / 1024.0f));
        float c1 = cospif((float)((k * j1) & 2047) * (1.0f / 1024.0f));
        float c2 = cospif((float)((k * j2) & 2047) * (1.0f / 1024.0f));
        float c3 = cospif((float)((k * j3) & 2047) * (1.0f / 1024.0f));
        s0 += (double)(c0 / ((float)j0 * (float)j0));
        s1 += (double)(c1 / ((float)j1 * (float)j1));
        s2 += (double)(c2 / ((float)j2 * (float)j2));
        s3 += (double)(c3 / ((float)j3 * (float)j3));
    }
    double four = 0.5 - (4.0 / (M_PI * M_PI)) * ((s0 + s1) + (s2 + s3));
    if (k > 0) {
        double om = M_PI * (double)k / 2048.0;
        four *= sin(om) / om;
    }
    g_filt[k] = (float)four;
}

// ---------------------------------------------------------------------------
// Stage 0b: h[d] = irfft(FILT)[d]. One block per d, 128 threads + reduction.
// ---------------------------------------------------------------------------
__global__ void __launch_bounds__(128) hker_kernel() {
    __shared__ double red[128];
    int d = blockIdx.x;
    int tid = threadIdx.x;
    double s = 0.0;
    for (int k = 1 + tid; k <= 1023; k += 128) {
        s += (double)g_filt[k] * (double)cospif((float)((k * d) & 2047) * (1.0f / 1024.0f));
    }
    red[tid] = s;
    __syncthreads();
    for (int w = 64; w > 0; w >>= 1) {
        if (tid < w) red[tid] += red[tid + w];
        __syncthreads();
    }
    if (tid == 0) {
        double t = (double)g_filt[0] + (double)g_filt[1024] * ((d & 1) ? -1.0 : 1.0)
                 + 2.0 * red[0];
        float h = (float)(t * (1.0 / 2048.0) * (M_PI / (2.0 * (double)NAq)));
        g_hext[735 - d] = h;
        g_hext[735 + d] = h;
    }
}

// ---------------------------------------------------------------------------
// Stage 0c: angle tables
// ---------------------------------------------------------------------------
__global__ void angle_kernel() {
    int a = blockIdx.x * blockDim.x + threadIdx.x;
    if (a >= NAq) return;
    double beta = 2.0 * M_PI * (double)a / (double)NAq + M_PI / 2.0;
    g_cos[a] = (float)cos(beta);
    g_sin[a] = (float)sin(beta);
}

// ---------------------------------------------------------------------------
// Stage 1: filtering as linear convolution, 4 rows/block; emits (v, dv) pairs.
// ---------------------------------------------------------------------------
#define RB 4
__global__ void __launch_bounds__(256) conv_kernel(const float* __restrict__ sino) {
    __shared__ float s_s[RB][NDq];
    __shared__ float s_h[1536];
    int tid = threadIdx.x;
    int row0 = blockIdx.x * RB;
#pragma unroll
    for (int r = 0; r < RB; r++)
        for (int i = tid; i < NDq; i += 256)
            s_s[r][i] = sino[(row0 + r) * NDq + i];
    for (int i = tid; i < 1536; i += 256) s_h[i] = (i < 1471) ? g_hext[i] : 0.0f;
    __syncthreads();

    float acc[RB][3] = {};
    const float* h0 = s_h + tid + 735;
#pragma unroll 4
    for (int k = 0; k < NDq; k++) {
        float hv0 = h0[-k];
        float hv1 = h0[256 - k];
        float hv2 = h0[512 - k];
#pragma unroll
        for (int r = 0; r < RB; r++) {
            float sv = s_s[r][k];
            acc[r][0] = fmaf(sv, hv0, acc[r][0]);
            acc[r][1] = fmaf(sv, hv1, acc[r][1]);
            acc[r][2] = fmaf(sv, hv2, acc[r][2]);
        }
    }
    __syncthreads();
#pragma unroll
    for (int r = 0; r < RB; r++) {
        s_s[r][tid] = acc[r][0];
        s_s[r][tid + 256] = acc[r][1];
        if (tid < NDq - 512) s_s[r][tid + 512] = acc[r][2];
    }
    __syncthreads();
#pragma unroll
    for (int r = 0; r < RB; r++) {
        float2* dst = g_fp2 + (row0 + r) * NDq;
        for (int i = tid; i < NDq; i += 256) {
            float v = s_s[r][i];
            float vn = (i < NDq - 1) ? s_s[r][i + 1] : v;
            dst[i] = make_float2(v, vn - v);
        }
    }
}

// ---------------------------------------------------------------------------
// Stage 2: fan-beam backprojection, 4-way angle split (blockIdx.z).
// 32x32 tile; lane = x (conflict-friendly gather), thread iterates 4 y.
// cp.async double-buffered chunks of 4 angles; smem-staged cos/sin.
// Interior tiles (provably in-range detector index) take a clamp-free path.
// ---------------------------------------------------------------------------
__global__ void __launch_bounds__(256, 4) bp_kernel() {
    __shared__ float2 sbuf[2][CHP];      // 2 * 23552 B
    __shared__ float2 s_trig[2][CH];
    int tid = threadIdx.x;
    int z   = blockIdx.z;
    int lx  = tid & 31;                  // lane = x offset
    int wy  = tid >> 5;                  // warp = 4-row band
    int x   = blockIdx.x * 32 + lx;
    int y0  = blockIdx.y * 32 + wy * 4;

    float xs  = (float)x  - 255.5f;
    float ys0 = (float)y0 - 255.5f;

    const float Df = (float)Dd;
    const float K  = (float)(DSDd / DUd);
    const float C  = ((float)NDq - 1.0f) * 0.5f;

    // tile classification: farthest-corner radius bound
    float tx0 = (float)(blockIdx.x * 32) - 255.5f;
    float ty0 = (float)(blockIdx.y * 32) - 255.5f;
    float mx = fmaxf(fabsf(tx0), fabsf(tx0 + 31.0f));
    float my = fmaxf(fabsf(ty0), fabsf(ty0 + 31.0f));
    float rm = sqrtf(mx * mx + my * my);
    bool fast = (K * rm) < (367.0f * (Df - rm));

    unsigned int sb0a = (unsigned int)__cvta_generic_to_shared(&sbuf[0][0]);
    unsigned int sb1a = (unsigned int)__cvta_generic_to_shared(&sbuf[1][0]);
    const float4* gsrc = (const float4*)(g_fp2 + z * APB * NDq);
    int abase = z * APB;

    // preload chunk 0 (+ its trig)
#pragma unroll
    for (int j = 0; j < 6; j++) {
        int idx = tid + j * 256;
        if (idx < CHP4) cpasync16(sb0a + idx * 16, gsrc + idx);
    }
    if (tid < CH) s_trig[0][tid] = make_float2(g_cos[abase + tid], g_sin[abase + tid]);
    cpasync_commit();
    cpasync_wait0();
    __syncthreads();

    float acc[4] = {0.f, 0.f, 0.f, 0.f};

    for (int c = 0; c < NCHb; c++) {
        if (c + 1 < NCHb) {
            const float4* src = gsrc + (c + 1) * CHP4;
            unsigned int dst = (c & 1) ? sb0a : sb1a;
#pragma unroll
            for (int j = 0; j < 6; j++) {
                int idx = tid + j * 256;
                if (idx < CHP4) cpasync16(dst + idx * 16, src + idx);
            }
            if (tid < CH) {
                int a = abase + (c + 1) * CH + tid;
                s_trig[(c + 1) & 1][tid] = make_float2(g_cos[a], g_sin[a]);
            }
        }
        cpasync_commit();

        const float2* buf = sbuf[c & 1];
        const float2* trg = s_trig[c & 1];

        if (fast) {
#pragma unroll
            for (int aa = 0; aa < CH; aa++) {
                float2 cs = trg[aa];
                float cb = cs.x, sb = cs.y;
                const float2* row = buf + aa * NDq;

                float den = Df - fmaf(xs, cb, ys0 * sb);
                float peK = fmaf(ys0, cb, -xs * sb) * K;
                float cbK = cb * K;
                float r0  = frcp(den);
                float e   = sb * r0;
                float t   = 0.0f;
                float r   = r0;
#pragma unroll
                for (int i = 0; i < 4; i++) {
                    float iu = fmaf(peK, r, C);        // in (0.5, 734.5)
                    int   i0 = __float2int_rd(iu);
                    float fr = iu - __int2float_rn(i0);
                    float2 v = row[i0];
                    float val = fmaf(fr, v.y, v.x);
                    acc[i] = fmaf(r * r, val, acc[i]);
                    t += e;
                    peK += cbK;
                    float f = fmaf(t, t, t);
                    r = fmaf(r0, f, r0);
                }
            }
        } else {
#pragma unroll
            for (int aa = 0; aa < CH; aa++) {
                float2 cs = trg[aa];
                float cb = cs.x, sb = cs.y;
                const float2* row = buf + aa * NDq;

                float den = Df - fmaf(xs, cb, ys0 * sb);
                float peK = fmaf(ys0, cb, -xs * sb) * K;
                float cbK = cb * K;
                float r0  = frcp(den);
                float e   = sb * r0;
                float t   = 0.0f;
                float r   = r0;
#pragma unroll
                for (int i = 0; i < 4; i++) {
                    float iu = fmaf(peK, r, C);
                    int   i0 = __float2int_rd(iu);
                    float fr = iu - __int2float_rn(i0);
                    int   ic = min(max(i0, 0), NDq - 2);
                    float2 v = row[ic];
                    float val = fmaf(fr, v.y, v.x);
                    float w  = ((unsigned)i0 < (unsigned)(NDq - 1)) ? r * r : 0.0f;
                    acc[i] = fmaf(w, val, acc[i]);
                    t += e;
                    peK += cbK;
                    float f = fmaf(t, t, t);
                    r = fmaf(r0, f, r0);
                }
            }
        }

        cpasync_wait0();
        __syncthreads();
    }

    float* dst = g_part[z] + y0 * NPq + x;
#pragma unroll
    for (int i = 0; i < 4; i++) dst[i * NPq] = acc[i];
}

// ---------------------------------------------------------------------------
// Stage 3: sum the 4 partial planes + HU normalization.
// ---------------------------------------------------------------------------
__global__ void __launch_bounds__(128) reduce_kernel(float* __restrict__ out) {
    const float A = (float)((Dd * Dd) * (1000.0 / 0.0192) / 4096.0);
    const float B = (float)(24.0 / 4096.0);
    int idx = blockIdx.x * 128 + threadIdx.x;      // float4 index
    float4 p0 = ((const float4*)g_part[0])[idx];
    float4 p1 = ((const float4*)g_part[1])[idx];
    float4 p2 = ((const float4*)g_part[2])[idx];
    float4 p3 = ((const float4*)g_part[3])[idx];
    float4 o;
    o.x = fmaf(A, (p0.x + p1.x) + (p2.x + p3.x), B);
    o.y = fmaf(A, (p0.y + p1.y) + (p2.y + p3.y), B);
    o.z = fmaf(A, (p0.z + p1.z) + (p2.z + p3.z), B);
    o.w = fmaf(A, (p0.w + p1.w) + (p2.w + p3.w), B);
    ((float4*)out)[idx] = o;
}

// ---------------------------------------------------------------------------
extern "C" void kernel_launch(void* const* d_in, const int* in_sizes, int n_in,
                              void* d_out, int out_size) {
    const float* sino = (const float*)d_in[0];
    float* out = (float*)d_out;

    filt_kernel<<<9, 128>>>();              // 1025 values
    hker_kernel<<<NDq, 128>>>();            // 736 values, block-parallel
    angle_kernel<<<9, 128>>>();             // 1152 angles
    conv_kernel<<<NAq / RB, 256>>>(sino);   // filtered sinogram -> (v, dv) pairs
    dim3 grid(NPq / 32, NPq / 32, SPLIT);   // 16 x 16 x 4
    bp_kernel<<<grid, 256>>>();
    reduce_kernel<<<NPq * NPq / 4 / 128, 128>>>(out);
}